// round 2
// baseline (speedup 1.0000x reference)
#include <cuda_runtime.h>
#include <cuda_bf16.h>

#define LT_W 0.5f
#define LIN_W 0.1f

__global__ void __launch_bounds__(256) apply_lt_lin_v4(
    const float4* __restrict__ x, float4* __restrict__ out, int n4)
{
    int i = blockIdx.x * blockDim.x + threadIdx.x;
    if (i < n4) {
        float4 v = x[i];
        v.x = (v.x < LT_W) ? v.x * LIN_W : v.x;
        v.y = (v.y < LT_W) ? v.y * LIN_W : v.y;
        v.z = (v.z < LT_W) ? v.z * LIN_W : v.z;
        v.w = (v.w < LT_W) ? v.w * LIN_W : v.w;
        out[i] = v;
    }
}

// Scalar tail (not needed for n % 4 == 0, but keep it correct for any n)
__global__ void apply_lt_lin_tail(
    const float* __restrict__ x, float* __restrict__ out, int start, int n)
{
    int i = start + blockIdx.x * blockDim.x + threadIdx.x;
    if (i < n) {
        float v = x[i];
        out[i] = (v < LT_W) ? v * LIN_W : v;
    }
}

extern "C" void kernel_launch(void* const* d_in, const int* in_sizes, int n_in,
                              void* d_out, int out_size)
{
    const float* x = (const float*)d_in[0];
    float* out = (float*)d_out;
    int n = in_sizes[0];

    int n4 = n / 4;
    if (n4 > 0) {
        int threads = 256;
        int blocks = (n4 + threads - 1) / threads;
        apply_lt_lin_v4<<<blocks, threads>>>(
            (const float4*)x, (float4*)out, n4);
    }
    int rem = n - n4 * 4;
    if (rem > 0) {
        apply_lt_lin_tail<<<1, 128>>>(x, out, n4 * 4, n);
    }
}